// round 9
// baseline (speedup 1.0000x reference)
#include <cuda_runtime.h>
#include <math.h>

#define B_ 16
#define C_ 64
#define H_ 192
#define W_ 192
#define R_ 64

// ---------------- scratch (device globals; no allocation) ----------------
__device__ float g_cp[B_ * C_];            // [B][C]
__device__ float g_hp[B_ * H_];            // [B][H]
__device__ float g_wp[B_ * W_];            // [B][W]
__device__ float g_RS[B_ * C_ * H_];       // per-plane row sums  [B][C][H]
__device__ float g_CS[B_ * C_ * W_];       // per-plane col sums  [B][C][W]
__device__ float g_T [B_ * R_ * C_];       // p[r]*sigmoid(Cw)    [B][R][C]
__device__ float g_Hw[B_ * H_ * R_];       // sigmoid(Hw)         [B][H][R]
__device__ float g_Ww[B_ * R_ * W_];       // sigmoid(Ww)         [B][R][W]

// ---------------- f32x2 helpers (Blackwell packed fp32) -------------------
__device__ __forceinline__ unsigned long long pk2(float x, float y) {
    unsigned long long r;
    asm("mov.b64 %0, {%1, %2};" : "=l"(r) : "f"(x), "f"(y));
    return r;
}
__device__ __forceinline__ void fma2(unsigned long long& d,
                                     unsigned long long a,
                                     unsigned long long b) {
    asm("fma.rn.f32x2 %0, %1, %2, %3;" : "=l"(d) : "l"(a), "l"(b), "l"(d));
}
__device__ __forceinline__ float2 upk2(unsigned long long v) {
    float2 f;
    asm("mov.b64 {%0, %1}, %2;" : "=f"(f.x), "=f"(f.y) : "l"(v));
    return f;
}

__device__ __forceinline__ float sigmoidf_(float x) {
    return 1.0f / (1.0f + expf(-x));
}

// Multi-value butterfly: reduce acc[0..15] (one per batch) across 32 lanes
// with 16 shfls. Afterwards lane pairs hold in acc[0] the full sum for
// batch lane>>1; even lanes are the designated writers.
__device__ __forceinline__ void butterfly16(float (&acc)[B_], int lane) {
    #pragma unroll
    for (int off = 16; off >= 2; off >>= 1) {
        const int nv = off >> 1;
        const bool hi = (lane & off) != 0;
        #pragma unroll
        for (int j = 0; j < nv; j++) {
            float send = hi ? acc[j] : acc[j + nv];
            float recv = __shfl_xor_sync(0xffffffffu, send, off);
            acc[j] = (hi ? acc[j + nv] : acc[j]) + recv;
        }
    }
    acc[0] += __shfl_xor_sync(0xffffffffu, acc[0], 1);
}

// ---------------- kernel 1: per-plane pools ------------------------------
__global__ void __launch_bounds__(192) pool_kernel(const float* __restrict__ X) {
    const int c = blockIdx.x;
    const int b = blockIdx.y;
    const float* plane = X + ((b * C_ + c) * H_) * (long)W_;

    const int tid  = threadIdx.x;
    const int warp = tid >> 5;
    const int lane = tid & 31;

    __shared__ float scs[6][W_];
    __shared__ float swt[6];

    float col0 = 0.f, col1 = 0.f, col2 = 0.f, col3 = 0.f, col4 = 0.f, col5 = 0.f;
    float tot = 0.f;

    const int h0 = warp * 32;
    for (int i = 0; i < 32; i++) {
        const int h = h0 + i;
        const float* row = plane + h * W_;
        float v0 = row[lane +   0];
        float v1 = row[lane +  32];
        float v2 = row[lane +  64];
        float v3 = row[lane +  96];
        float v4 = row[lane + 128];
        float v5 = row[lane + 160];
        col0 += v0; col1 += v1; col2 += v2; col3 += v3; col4 += v4; col5 += v5;
        float rs = ((v0 + v1) + (v2 + v3)) + (v4 + v5);
        #pragma unroll
        for (int off = 16; off >= 1; off >>= 1)
            rs += __shfl_down_sync(0xffffffffu, rs, off);
        if (lane == 0) {
            g_RS[(b * C_ + c) * H_ + h] = rs;
            tot += rs;
        }
    }
    scs[warp][lane +   0] = col0;
    scs[warp][lane +  32] = col1;
    scs[warp][lane +  64] = col2;
    scs[warp][lane +  96] = col3;
    scs[warp][lane + 128] = col4;
    scs[warp][lane + 160] = col5;
    if (lane == 0) swt[warp] = tot;
    __syncthreads();

    float cs = 0.f;
    #pragma unroll
    for (int j = 0; j < 6; j++) cs += scs[j][tid];
    g_CS[(b * C_ + c) * W_ + tid] = cs;

    if (tid == 0) {
        float t = 0.f;
        #pragma unroll
        for (int j = 0; j < 6; j++) t += swt[j];
        g_cp[b * C_ + c] = t * (1.0f / (H_ * (float)W_));
    }
}

// ---------------- kernel 2: reduce RS/CS over c -> hp, wp ----------------
__global__ void hw_pool_kernel() {
    const int i = blockIdx.x * blockDim.x + threadIdx.x;  // 0 .. B*H-1
    if (i >= B_ * H_) return;
    const int b = i / H_;
    const int h = i - b * H_;
    float s1 = 0.f, s2 = 0.f;
    for (int c = 0; c < C_; c++) {
        s1 += g_RS[(b * C_ + c) * H_ + h];
        s2 += g_CS[(b * C_ + c) * W_ + h];
    }
    g_hp[i] = s1 * (1.0f / (C_ * (float)W_));
    g_wp[i] = s2 * (1.0f / (C_ * (float)H_));
}

// ---------------- kernel 3: ALL sigmoid weights, warp-per-2-rows GEMV ----
// blockIdx.y: 0 = H branch (Wh,bh -> g_Hw), 1 = W branch (Ww,bw -> g_Ww),
//             2 = C branch (Wc,bc,p -> g_T; only blockIdx.x < 256 active).
__global__ void __launch_bounds__(256) weights_kernel(
        const float* __restrict__ Wh, const float* __restrict__ bh,
        const float* __restrict__ Wwp, const float* __restrict__ bw,
        const float* __restrict__ Wc, const float* __restrict__ bc,
        const float* __restrict__ p) {
    const int tid  = threadIdx.x;
    const int warp = tid >> 5;
    const int lane = tid & 31;
    const int branch = blockIdx.y;

    if (branch == 2 && blockIdx.x >= (R_ * C_) / 16) return;

    __shared__ float sp[B_][H_];

    if (branch == 2) {
        // ---- C branch: rows of 64 ----
        for (int i = tid; i < B_ * C_; i += 256)
            sp[i >> 6][i & 63] = g_cp[i];
        __syncthreads();

        const int m0 = blockIdx.x * 16 + warp * 2;   // 0..4094
        const int m1 = m0 + 1;
        const float* w0 = Wc + m0 * C_;
        const float* w1 = Wc + m1 * C_;
        const float a0 = w0[lane], a1 = w0[lane + 32];
        const float b0 = w1[lane], b1 = w1[lane + 32];

        float acc0[B_], acc1[B_];
        #pragma unroll
        for (int b = 0; b < B_; b++) {
            const float p0 = sp[b][lane], p1 = sp[b][lane + 32];
            acc0[b] = fmaf(a1, p1, a0 * p0);
            acc1[b] = fmaf(b1, p1, b0 * p0);
        }
        butterfly16(acc0, lane);
        butterfly16(acc1, lane);

        if ((lane & 1) == 0) {
            const int batch = lane >> 1;
            const int r0 = m0 >> 6, d0 = m0 & 63;
            const int r1 = m1 >> 6, d1 = m1 & 63;
            g_T[(batch * R_ + r0) * C_ + d0] = p[r0] * sigmoidf_(acc0[0] + bc[m0]);
            g_T[(batch * R_ + r1) * C_ + d1] = p[r1] * sigmoidf_(acc1[0] + bc[m1]);
        }
        return;
    }

    // ---- H/W branches: rows of 192 ----
    {
        const float* pool = branch ? g_wp : g_hp;
        for (int i = tid; i < B_ * H_; i += 256)
            sp[i / H_][i - (i / H_) * H_] = pool[i];
    }
    __syncthreads();

    const int m0 = blockIdx.x * 16 + warp * 2;   // 0..12286
    const int m1 = m0 + 1;
    const float* Wsrc = branch ? Wwp : Wh;
    const float* bsrc = branch ? bw  : bh;
    const float* wrow0 = Wsrc + (long)m0 * H_;
    const float* wrow1 = Wsrc + (long)m1 * H_;

    float wa[6], wb[6];
    #pragma unroll
    for (int k = 0; k < 6; k++) wa[k] = wrow0[lane + 32 * k];
    #pragma unroll
    for (int k = 0; k < 6; k++) wb[k] = wrow1[lane + 32 * k];

    float acc0[B_], acc1[B_];
    #pragma unroll
    for (int b = 0; b < B_; b++) {
        float s0 = wa[0] * sp[b][lane];
        float s1 = wb[0] * sp[b][lane];
        #pragma unroll
        for (int k = 1; k < 6; k++) {
            const float pv = sp[b][lane + 32 * k];
            s0 = fmaf(wa[k], pv, s0);
            s1 = fmaf(wb[k], pv, s1);
        }
        acc0[b] = s0;
        acc1[b] = s1;
    }
    butterfly16(acc0, lane);
    butterfly16(acc1, lane);

    if ((lane & 1) == 0) {
        const int batch = lane >> 1;
        const int r0 = m0 / H_, d0 = m0 - r0 * H_;
        const int r1 = m1 / H_, d1 = m1 - r1 * H_;
        const float v0 = sigmoidf_(acc0[0] + bsrc[m0]);
        const float v1 = sigmoidf_(acc1[0] + bsrc[m1]);
        if (branch == 0) {
            g_Hw[(batch * H_ + d0) * R_ + r0] = v0;   // [B][H][R]
            g_Hw[(batch * H_ + d1) * R_ + r1] = v1;
        } else {
            g_Ww[(batch * R_ + r0) * W_ + d0] = v0;   // [B][R][W]
            g_Ww[(batch * R_ + r1) * W_ + d1] = v1;
        }
    }
}

// ---------------- kernel 4: main fused GEMM + elementwise ----------------
// Block = (h, b), 192 threads, FULL 192-w row. Smem (dynamic 64.3 KB):
//   sM[r][c] = T[b][r][c]*Hw[b][h][r] (64x64), sV[r][w] = Ww[b][r][w] (64x192).
// Thread tile 8c x 8w (32 f32x2 accumulators): per r only 4 LDS.128
// (each <=128B distinct; tc=tid&7 / tw=tid>>3 lane map) feeding 32 FFMA2
// -> crossbar-phase:fma ratio <=0.5 (was ~1.5 with the 8cx4w tile).
extern __shared__ float smem_dyn[];
__global__ void __launch_bounds__(192, 2) main_kernel(const float* __restrict__ X,
                                                      float* __restrict__ out) {
    const int h = blockIdx.x;   // 0..191
    const int b = blockIdx.y;   // 0..15

    float* sM = smem_dyn;                    // 4096 floats
    float* sV = smem_dyn + R_ * C_;          // 12288 floats
    float* sh = smem_dyn + R_ * C_ + R_ * W_;// 64 floats

    const int tid = threadIdx.x;
    const int tc  = tid & 7;     // c group: c = 8*tc .. 8*tc+7
    const int tw  = tid >> 3;    // w group: w = 8*tw .. 8*tw+7  (0..23)

    if (tid < R_) sh[tid] = g_Hw[(b * H_ + h) * R_ + tid];
    __syncthreads();

    // fill M = T * hw   (T layout [B][R][C], coalesced float4)
    {
        const float4* T4  = (const float4*)(g_T + b * (R_ * C_));
        float4*       sM4 = (float4*)sM;
        for (int i = tid; i < (R_ * C_) / 4; i += 192) {
            float4 t = T4[i];
            const float hv = sh[i >> 4];  // r = i / 16
            t.x *= hv; t.y *= hv; t.z *= hv; t.w *= hv;
            sM4[i] = t;
        }
    }
    // fill V (straight copy of g_Ww[b], contiguous)
    {
        const float4* Wb4 = (const float4*)(g_Ww + b * (R_ * W_));
        float4*       sV4 = (float4*)sV;
        for (int i = tid; i < (R_ * W_) / 4; i += 192)
            sV4[i] = Wb4[i];
    }
    __syncthreads();

    const ulonglong2* sM2 = (const ulonglong2*)sM;  // 16 per row of 64 floats
    const float4*     sV4 = (const float4*)sV;      // 48 per row of 192

    unsigned long long acc[4][8];  // [c-pair][w]
    #pragma unroll
    for (int i = 0; i < 4; i++)
        #pragma unroll
        for (int j = 0; j < 8; j++) acc[i][j] = 0ull;

    #pragma unroll 4
    for (int r = 0; r < R_; r++) {
        const ulonglong2 ma = sM2[r * 16 + 2 * tc];      // c pairs (0,1)
        const ulonglong2 mb = sM2[r * 16 + 2 * tc + 1];  // c pairs (2,3)
        const float4     v0 = sV4[r * 48 + 2 * tw];      // w 0..3
        const float4     v1 = sV4[r * 48 + 2 * tw + 1];  // w 4..7

        const unsigned long long B0 = pk2(v0.x, v0.x);
        const unsigned long long B1 = pk2(v0.y, v0.y);
        const unsigned long long B2 = pk2(v0.z, v0.z);
        const unsigned long long B3 = pk2(v0.w, v0.w);
        const unsigned long long B4 = pk2(v1.x, v1.x);
        const unsigned long long B5 = pk2(v1.y, v1.y);
        const unsigned long long B6 = pk2(v1.z, v1.z);
        const unsigned long long B7 = pk2(v1.w, v1.w);

        fma2(acc[0][0], ma.x, B0); fma2(acc[0][1], ma.x, B1);
        fma2(acc[0][2], ma.x, B2); fma2(acc[0][3], ma.x, B3);
        fma2(acc[0][4], ma.x, B4); fma2(acc[0][5], ma.x, B5);
        fma2(acc[0][6], ma.x, B6); fma2(acc[0][7], ma.x, B7);
        fma2(acc[1][0], ma.y, B0); fma2(acc[1][1], ma.y, B1);
        fma2(acc[1][2], ma.y, B2); fma2(acc[1][3], ma.y, B3);
        fma2(acc[1][4], ma.y, B4); fma2(acc[1][5], ma.y, B5);
        fma2(acc[1][6], ma.y, B6); fma2(acc[1][7], ma.y, B7);
        fma2(acc[2][0], mb.x, B0); fma2(acc[2][1], mb.x, B1);
        fma2(acc[2][2], mb.x, B2); fma2(acc[2][3], mb.x, B3);
        fma2(acc[2][4], mb.x, B4); fma2(acc[2][5], mb.x, B5);
        fma2(acc[2][6], mb.x, B6); fma2(acc[2][7], mb.x, B7);
        fma2(acc[3][0], mb.y, B0); fma2(acc[3][1], mb.y, B1);
        fma2(acc[3][2], mb.y, B2); fma2(acc[3][3], mb.y, B3);
        fma2(acc[3][4], mb.y, B4); fma2(acc[3][5], mb.y, B5);
        fma2(acc[3][6], mb.y, B6); fma2(acc[3][7], mb.y, B7);
    }

    // epilogue: each c-pair cp covers c = 8*tc + 2*cp (q.x) and c+1 (q.y)
    const int w0 = tw * 8;
    #pragma unroll
    for (int cp = 0; cp < 4; cp++) {
        float2 q0 = upk2(acc[cp][0]);
        float2 q1 = upk2(acc[cp][1]);
        float2 q2 = upk2(acc[cp][2]);
        float2 q3 = upk2(acc[cp][3]);
        float2 q4 = upk2(acc[cp][4]);
        float2 q5 = upk2(acc[cp][5]);
        float2 q6 = upk2(acc[cp][6]);
        float2 q7 = upk2(acc[cp][7]);

        const int c0 = 8 * tc + 2 * cp;
        const long i0 = ((long)(b * C_ + c0) * H_ + h) * W_ + w0;
        const long i1 = i0 + (long)H_ * W_;

        float4 xa = *(const float4*)(X + i0);
        float4 xb = *(const float4*)(X + i0 + 4);
        float4 oa, ob;
        oa.x = q0.x * xa.x; oa.y = q1.x * xa.y; oa.z = q2.x * xa.z; oa.w = q3.x * xa.w;
        ob.x = q4.x * xb.x; ob.y = q5.x * xb.y; ob.z = q6.x * xb.z; ob.w = q7.x * xb.w;
        *(float4*)(out + i0)     = oa;
        *(float4*)(out + i0 + 4) = ob;

        float4 xc = *(const float4*)(X + i1);
        float4 xd = *(const float4*)(X + i1 + 4);
        float4 oc, od;
        oc.x = q0.y * xc.x; oc.y = q1.y * xc.y; oc.z = q2.y * xc.z; oc.w = q3.y * xc.w;
        od.x = q4.y * xd.x; od.y = q5.y * xd.y; od.z = q6.y * xd.z; od.w = q7.y * xd.w;
        *(float4*)(out + i1)     = oc;
        *(float4*)(out + i1 + 4) = od;
    }
}

// ---------------- launch ---------------------------------------------------
extern "C" void kernel_launch(void* const* d_in, const int* in_sizes, int n_in,
                              void* d_out, int out_size) {
    const float* X   = (const float*)d_in[0];
    const float* p   = (const float*)d_in[1];
    const float* Wc  = (const float*)d_in[2];
    const float* bc  = (const float*)d_in[3];
    const float* Wh  = (const float*)d_in[4];
    const float* bh  = (const float*)d_in[5];
    const float* Wwp = (const float*)d_in[6];
    const float* bw  = (const float*)d_in[7];
    float* out = (float*)d_out;

    const int main_smem = (R_ * C_ + R_ * W_ + R_) * (int)sizeof(float); // 65792 B
    static int attr_done = 0;
    if (!attr_done) {
        cudaFuncSetAttribute(main_kernel,
                             cudaFuncAttributeMaxDynamicSharedMemorySize,
                             main_smem);
        attr_done = 1;
    }

    pool_kernel<<<dim3(C_, B_), 192>>>(X);                               // 1
    hw_pool_kernel<<<(B_ * H_ + 255) / 256, 256>>>();                    // 2
    weights_kernel<<<dim3((R_ * H_) / 16, 3), 256>>>(Wh, bh, Wwp, bw,    // 3
                                                     Wc, bc, p);
    main_kernel<<<dim3(H_, B_), 192, main_smem>>>(X, out);               // 4
}

// round 11
// speedup vs baseline: 2.0690x; 2.0690x over previous
#include <cuda_runtime.h>
#include <math.h>

#define B_ 16
#define C_ 64
#define H_ 192
#define W_ 192
#define R_ 64

// ---------------- scratch (device globals; no allocation) ----------------
__device__ float g_cp[B_ * C_];            // [B][C]
__device__ float g_hp[B_ * H_];            // [B][H]
__device__ float g_wp[B_ * W_];            // [B][W]
__device__ float g_RS[B_ * C_ * H_];       // per-plane row sums  [B][C][H]
__device__ float g_CS[B_ * C_ * W_];       // per-plane col sums  [B][C][W]
__device__ float g_T [B_ * R_ * C_];       // p[r]*sigmoid(Cw)    [B][R][C]
__device__ float g_Hw[B_ * H_ * R_];       // sigmoid(Hw)         [B][H][R]
__device__ float g_Ww[B_ * R_ * W_];       // sigmoid(Ww)         [B][R][W]

// ---------------- f32x2 helpers (Blackwell packed fp32) -------------------
__device__ __forceinline__ unsigned long long pk2(float x, float y) {
    unsigned long long r;
    asm("mov.b64 %0, {%1, %2};" : "=l"(r) : "f"(x), "f"(y));
    return r;
}
__device__ __forceinline__ void fma2(unsigned long long& d,
                                     unsigned long long a,
                                     unsigned long long b) {
    asm("fma.rn.f32x2 %0, %1, %2, %3;" : "=l"(d) : "l"(a), "l"(b), "l"(d));
}
__device__ __forceinline__ unsigned long long add2(unsigned long long a,
                                                   unsigned long long b) {
    unsigned long long r;
    asm("add.rn.f32x2 %0, %1, %2;" : "=l"(r) : "l"(a), "l"(b));
    return r;
}
__device__ __forceinline__ float2 upk2(unsigned long long v) {
    float2 f;
    asm("mov.b64 {%0, %1}, %2;" : "=f"(f.x), "=f"(f.y) : "l"(v));
    return f;
}
__device__ __forceinline__ unsigned long long shfl64(unsigned long long v, int off) {
    const unsigned lo = __shfl_xor_sync(0xffffffffu, (unsigned)(v & 0xffffffffu), off);
    const unsigned hi = __shfl_xor_sync(0xffffffffu, (unsigned)(v >> 32), off);
    return ((unsigned long long)hi << 32) | lo;
}

__device__ __forceinline__ float sigmoidf_(float x) {
    return 1.0f / (1.0f + expf(-x));
}

// Scalar multi-value butterfly (16 batches over 32 lanes, 17 shfls).
// Result: lane pairs hold in acc[0] the sum for batch lane>>1.
__device__ __forceinline__ void butterfly16(float (&acc)[B_], int lane) {
    #pragma unroll
    for (int off = 16; off >= 2; off >>= 1) {
        const int nv = off >> 1;
        const bool hi = (lane & off) != 0;
        #pragma unroll
        for (int j = 0; j < nv; j++) {
            float send = hi ? acc[j] : acc[j + nv];
            float recv = __shfl_xor_sync(0xffffffffu, send, off);
            acc[j] = (hi ? acc[j + nv] : acc[j]) + recv;
        }
    }
    acc[0] += __shfl_xor_sync(0xffffffffu, acc[0], 1);
}

// Packed butterfly: 8 f32x2 values (batch j in .lo, j+8 in .hi) over 32
// lanes. Offsets 16,8,4 consume the value index; 2,1 reduce. Result:
// lanes with equal lane>>2 hold in v[0] the packed sum for pair j=lane>>2.
__device__ __forceinline__ void butterfly8p(unsigned long long (&v)[8], int lane) {
    #pragma unroll
    for (int off = 16; off >= 4; off >>= 1) {
        const int nv = off >> 2;
        const bool hi = (lane & off) != 0;
        #pragma unroll
        for (int j = 0; j < nv; j++) {
            unsigned long long send = hi ? v[j] : v[j + nv];
            unsigned long long recv = shfl64(send, off);
            v[j] = add2(hi ? v[j + nv] : v[j], recv);
        }
    }
    v[0] = add2(v[0], shfl64(v[0], 2));
    v[0] = add2(v[0], shfl64(v[0], 1));
}

// ---------------- kernel 1: per-plane pools ------------------------------
__global__ void __launch_bounds__(192) pool_kernel(const float* __restrict__ X) {
    const int c = blockIdx.x;
    const int b = blockIdx.y;
    const float* plane = X + ((b * C_ + c) * H_) * (long)W_;

    const int tid  = threadIdx.x;
    const int warp = tid >> 5;
    const int lane = tid & 31;

    __shared__ float scs[6][W_];
    __shared__ float swt[6];

    float col0 = 0.f, col1 = 0.f, col2 = 0.f, col3 = 0.f, col4 = 0.f, col5 = 0.f;
    float tot = 0.f;

    const int h0 = warp * 32;
    for (int i = 0; i < 32; i++) {
        const int h = h0 + i;
        const float* row = plane + h * W_;
        float v0 = row[lane +   0];
        float v1 = row[lane +  32];
        float v2 = row[lane +  64];
        float v3 = row[lane +  96];
        float v4 = row[lane + 128];
        float v5 = row[lane + 160];
        col0 += v0; col1 += v1; col2 += v2; col3 += v3; col4 += v4; col5 += v5;
        float rs = ((v0 + v1) + (v2 + v3)) + (v4 + v5);
        #pragma unroll
        for (int off = 16; off >= 1; off >>= 1)
            rs += __shfl_down_sync(0xffffffffu, rs, off);
        if (lane == 0) {
            g_RS[(b * C_ + c) * H_ + h] = rs;
            tot += rs;
        }
    }
    scs[warp][lane +   0] = col0;
    scs[warp][lane +  32] = col1;
    scs[warp][lane +  64] = col2;
    scs[warp][lane +  96] = col3;
    scs[warp][lane + 128] = col4;
    scs[warp][lane + 160] = col5;
    if (lane == 0) swt[warp] = tot;
    __syncthreads();

    float cs = 0.f;
    #pragma unroll
    for (int j = 0; j < 6; j++) cs += scs[j][tid];
    g_CS[(b * C_ + c) * W_ + tid] = cs;

    if (tid == 0) {
        float t = 0.f;
        #pragma unroll
        for (int j = 0; j < 6; j++) t += swt[j];
        g_cp[b * C_ + c] = t * (1.0f / (H_ * (float)W_));
    }
}

// ---------------- kernel 2: reduce RS/CS over c -> hp, wp ----------------
__global__ void hw_pool_kernel() {
    const int i = blockIdx.x * blockDim.x + threadIdx.x;  // 0 .. B*H-1
    if (i >= B_ * H_) return;
    const int b = i / H_;
    const int h = i - b * H_;
    float s1 = 0.f, s2 = 0.f;
    for (int c = 0; c < C_; c++) {
        s1 += g_RS[(b * C_ + c) * H_ + h];
        s2 += g_CS[(b * C_ + c) * W_ + h];
    }
    g_hp[i] = s1 * (1.0f / (C_ * (float)W_));
    g_wp[i] = s2 * (1.0f / (C_ * (float)H_));
}

// ---------------- kernel 3: ALL sigmoid weights ---------------------------
// blockIdx.y: 0 = H branch, 1 = W branch, 2 = C branch.
// H/W: warp-per-2-rows GEMV with BATCH-PACKED f32x2 math: pools staged in
// smem as (b, b+8) ull pairs -> per k-step 1 LDS.64 + 1 FFMA2 covers 2
// batches. Packed 64-bit butterfly reduction.
__global__ void __launch_bounds__(256) weights_kernel(
        const float* __restrict__ Wh, const float* __restrict__ bh,
        const float* __restrict__ Wwp, const float* __restrict__ bw,
        const float* __restrict__ Wc, const float* __restrict__ bc,
        const float* __restrict__ p) {
    const int tid  = threadIdx.x;
    const int warp = tid >> 5;
    const int lane = tid & 31;
    const int branch = blockIdx.y;

    __shared__ unsigned long long sp2[8][H_];   // packed pools (b, b+8)
    __shared__ float spc[B_][C_];               // C-branch pools

    if (branch == 2) {
        if (blockIdx.x >= (R_ * C_) / 16) return;
        // ---- C branch: rows of 64, scalar path ----
        for (int i = tid; i < B_ * C_; i += 256)
            spc[i >> 6][i & 63] = g_cp[i];
        __syncthreads();

        const int m0 = blockIdx.x * 16 + warp * 2;   // 0..4094
        const int m1 = m0 + 1;
        const float* w0 = Wc + m0 * C_;
        const float* w1 = Wc + m1 * C_;
        const float a0 = w0[lane], a1 = w0[lane + 32];
        const float b0 = w1[lane], b1 = w1[lane + 32];

        float acc0[B_], acc1[B_];
        #pragma unroll
        for (int b = 0; b < B_; b++) {
            const float p0 = spc[b][lane], p1 = spc[b][lane + 32];
            acc0[b] = fmaf(a1, p1, a0 * p0);
            acc1[b] = fmaf(b1, p1, b0 * p0);
        }
        butterfly16(acc0, lane);
        butterfly16(acc1, lane);

        if ((lane & 1) == 0) {
            const int batch = lane >> 1;
            const int r0 = m0 >> 6, d0 = m0 & 63;
            const int r1 = m1 >> 6, d1 = m1 & 63;
            g_T[(batch * R_ + r0) * C_ + d0] = p[r0] * sigmoidf_(acc0[0] + bc[m0]);
            g_T[(batch * R_ + r1) * C_ + d1] = p[r1] * sigmoidf_(acc1[0] + bc[m1]);
        }
        return;
    }

    // ---- H/W branches: rows of 192, batch-packed path ----
    {
        const float* pool = branch ? g_wp : g_hp;
        for (int i = tid; i < 8 * H_; i += 256) {
            const int j = i / H_;
            const int h = i - j * H_;
            sp2[j][h] = pk2(pool[j * H_ + h], pool[(j + 8) * H_ + h]);
        }
    }
    __syncthreads();

    const int m0 = blockIdx.x * 16 + warp * 2;   // 0..12286
    const int m1 = m0 + 1;
    const float* Wsrc = branch ? Wwp : Wh;
    const float* bsrc = branch ? bw  : bh;
    const float* wrow0 = Wsrc + (long)m0 * H_;
    const float* wrow1 = Wsrc + (long)m1 * H_;

    float wa[6], wb[6];
    #pragma unroll
    for (int k = 0; k < 6; k++) wa[k] = wrow0[lane + 32 * k];
    #pragma unroll
    for (int k = 0; k < 6; k++) wb[k] = wrow1[lane + 32 * k];

    unsigned long long acc0[8], acc1[8];
    #pragma unroll
    for (int j = 0; j < 8; j++) { acc0[j] = 0ull; acc1[j] = 0ull; }

    #pragma unroll
    for (int k = 0; k < 6; k++) {
        const unsigned long long wA = pk2(wa[k], wa[k]);
        const unsigned long long wB = pk2(wb[k], wb[k]);
        const int hidx = lane + 32 * k;
        #pragma unroll
        for (int j = 0; j < 8; j++) {
            const unsigned long long pv = sp2[j][hidx];
            fma2(acc0[j], wA, pv);
            fma2(acc1[j], wB, pv);
        }
    }
    butterfly8p(acc0, lane);
    butterfly8p(acc1, lane);

    if ((lane & 3) == 0) {
        const int j  = lane >> 2;          // batch pair (j, j+8)
        const int r0 = m0 / H_, d0 = m0 - r0 * H_;
        const int r1 = m1 / H_, d1 = m1 - r1 * H_;
        const float bias0 = bsrc[m0];
        const float bias1 = bsrc[m1];
        const float2 q0 = upk2(acc0[0]);
        const float2 q1 = upk2(acc1[0]);
        const float v0a = sigmoidf_(q0.x + bias0);
        const float v0b = sigmoidf_(q0.y + bias0);
        const float v1a = sigmoidf_(q1.x + bias1);
        const float v1b = sigmoidf_(q1.y + bias1);
        if (branch == 0) {
            g_Hw[((j    ) * H_ + d0) * R_ + r0] = v0a;   // [B][H][R]
            g_Hw[((j + 8) * H_ + d0) * R_ + r0] = v0b;
            g_Hw[((j    ) * H_ + d1) * R_ + r1] = v1a;
            g_Hw[((j + 8) * H_ + d1) * R_ + r1] = v1b;
        } else {
            g_Ww[((j    ) * R_ + r0) * W_ + d0] = v0a;   // [B][R][W]
            g_Ww[((j + 8) * R_ + r0) * W_ + d0] = v0b;
            g_Ww[((j    ) * R_ + r1) * W_ + d1] = v1a;
            g_Ww[((j + 8) * R_ + r1) * W_ + d1] = v1b;
        }
    }
}

// ---------------- kernel 4: main fused GEMM + elementwise ----------------
// R7 geometry (measured-best): block = (h, w-half, b), 192 threads,
// static smem 40.3 KB, thread tile 8c x 4w (16 f32x2 accumulators).
// __launch_bounds__(192, 4) caps regs at 85 -> 4 blocks/SM (24 warps)
// for latency hiding (R9 showed occupancy is the binding constraint).
__global__ void __launch_bounds__(192, 4) main_kernel(const float* __restrict__ X,
                                                      float* __restrict__ out) {
    const int h    = blockIdx.x;   // 0..191
    const int half = blockIdx.y;   // 0..1
    const int b    = blockIdx.z;   // 0..15

    const int tid = threadIdx.x;
    const int tc  = tid / 24;      // 0..7
    const int tw  = tid - tc * 24; // 0..23

    __shared__ __align__(16) float sM[R_ * C_];   // 16 KB  [r][c]
    __shared__ __align__(16) float sV[R_ * 96];   // 24 KB  [r][w']
    __shared__ float sh[R_];

    if (tid < R_) sh[tid] = g_Hw[(b * H_ + h) * R_ + tid];
    __syncthreads();

    // fill M = T * hw   (T layout [B][R][C], coalesced float4)
    {
        const float4* T4  = (const float4*)(g_T + b * (R_ * C_));
        float4*       sM4 = (float4*)sM;
        for (int i = tid; i < (R_ * C_) / 4; i += 192) {
            float4 t = T4[i];
            const float hv = sh[i >> 4];  // r = i / 16
            t.x *= hv; t.y *= hv; t.z *= hv; t.w *= hv;
            sM4[i] = t;
        }
    }
    // fill V half
    {
        float4* sV4 = (float4*)sV;
        for (int i = tid; i < R_ * 24; i += 192) {
            const int r = i / 24;
            const int j = i - r * 24;
            sV4[r * 24 + j] =
                ((const float4*)(g_Ww + (b * R_ + r) * W_ + half * 96))[j];
        }
    }
    __syncthreads();

    const ulonglong2* sM2 = (const ulonglong2*)sM;  // 16 per row of 64 floats
    const float4*     sV4 = (const float4*)sV;      // 24 per row of 96

    unsigned long long acc[4][4];  // [c-pair][w]
    #pragma unroll
    for (int i = 0; i < 4; i++)
        #pragma unroll
        for (int j = 0; j < 4; j++) acc[i][j] = 0ull;

    #pragma unroll 8
    for (int r = 0; r < R_; r++) {
        const ulonglong2 m0 = sM2[r * 16 + tc];      // c = 4tc..4tc+3 (2 pairs)
        const ulonglong2 m1 = sM2[r * 16 + 8 + tc];  // c = 32+4tc..+3
        const float4     bv = sV4[r * 24 + tw];      // w = 4tw..4tw+3

        const unsigned long long Bx = pk2(bv.x, bv.x);
        const unsigned long long By = pk2(bv.y, bv.y);
        const unsigned long long Bz = pk2(bv.z, bv.z);
        const unsigned long long Bw = pk2(bv.w, bv.w);

        fma2(acc[0][0], m0.x, Bx); fma2(acc[0][1], m0.x, By);
        fma2(acc[0][2], m0.x, Bz); fma2(acc[0][3], m0.x, Bw);
        fma2(acc[1][0], m0.y, Bx); fma2(acc[1][1], m0.y, By);
        fma2(acc[1][2], m0.y, Bz); fma2(acc[1][3], m0.y, Bw);
        fma2(acc[2][0], m1.x, Bx); fma2(acc[2][1], m1.x, By);
        fma2(acc[2][2], m1.x, Bz); fma2(acc[2][3], m1.x, Bw);
        fma2(acc[3][0], m1.y, Bx); fma2(acc[3][1], m1.y, By);
        fma2(acc[3][2], m1.y, Bz); fma2(acc[3][3], m1.y, Bw);
    }

    // unpack: vals[ci][wj], ci: 0..3 -> c = 4tc+ci ; 4..7 -> c = 32+4tc+(ci-4)
    float vals[8][4];
    #pragma unroll
    for (int cp = 0; cp < 4; cp++) {
        #pragma unroll
        for (int wj = 0; wj < 4; wj++) {
            const float2 q = upk2(acc[cp][wj]);
            vals[2 * cp + 0][wj] = q.x;
            vals[2 * cp + 1][wj] = q.y;
        }
    }

    const int w0 = half * 96 + tw * 4;
    #pragma unroll
    for (int ci = 0; ci < 8; ci++) {
        const int c = (ci < 4) ? (tc * 4 + ci) : (32 + tc * 4 + (ci - 4));
        const int idx = ((b * C_ + c) * H_ + h) * W_ + w0;
        const float4 x = *(const float4*)(X + idx);
        float4 o;
        o.x = vals[ci][0] * x.x;
        o.y = vals[ci][1] * x.y;
        o.z = vals[ci][2] * x.z;
        o.w = vals[ci][3] * x.w;
        *(float4*)(out + idx) = o;
    }
}

// ---------------- launch ---------------------------------------------------
extern "C" void kernel_launch(void* const* d_in, const int* in_sizes, int n_in,
                              void* d_out, int out_size) {
    const float* X   = (const float*)d_in[0];
    const float* p   = (const float*)d_in[1];
    const float* Wc  = (const float*)d_in[2];
    const float* bc  = (const float*)d_in[3];
    const float* Wh  = (const float*)d_in[4];
    const float* bh  = (const float*)d_in[5];
    const float* Wwp = (const float*)d_in[6];
    const float* bw  = (const float*)d_in[7];
    float* out = (float*)d_out;

    pool_kernel<<<dim3(C_, B_), 192>>>(X);                               // 1
    hw_pool_kernel<<<(B_ * H_ + 255) / 256, 256>>>();                    // 2
    weights_kernel<<<dim3((R_ * H_) / 16, 3), 256>>>(Wh, bh, Wwp, bw,    // 3
                                                     Wc, bc, p);
    main_kernel<<<dim3(H_, 2, B_), 192>>>(X, out);                       // 4
}